// round 13
// baseline (speedup 1.0000x reference)
#include <cuda_runtime.h>
#include <cstdint>

#define MARGIN 0.1f
#define RPT 32                          // rows per TMA tile
#define TILE_FLOATS (RPT * 128)         // 4096
#define TILE_BYTES  (TILE_FLOATS * 4)   // 16384
#define LAB_BYTES   (RPT * 4)           // 128
#define RPB 4                           // rows per LDG batch
#define NUM_BLOCKS 592                  // 148 SMs * 4 CTAs
// Persistent (L2-retained, TMA/evict-normal) fraction of rows: 13/16.
// 13/16 * 262144 rows * 512 B = 109.0 MB < 126 MB L2.
#define P_NUM 13
#define P_DEN 16

// Persistent device scratch; reset by last block each call (graph-replay safe).
__device__ double       g_total = 0.0;
__device__ unsigned int g_count = 0u;

__device__ __forceinline__ uint32_t smem_u32(const void* p) {
    return (uint32_t)__cvta_generic_to_shared(p);
}
__device__ __forceinline__ void mbar_init(uint32_t a, uint32_t cnt) {
    asm volatile("mbarrier.init.shared.b64 [%0], %1;" :: "r"(a), "r"(cnt) : "memory");
}
__device__ __forceinline__ void mbar_expect_tx(uint32_t a, uint32_t bytes) {
    asm volatile("mbarrier.arrive.expect_tx.shared.b64 _, [%0], %1;"
                 :: "r"(a), "r"(bytes) : "memory");
}
__device__ __forceinline__ void bulk_g2s(uint32_t dst, const void* src,
                                         uint32_t bytes, uint32_t mbar) {
    asm volatile(
        "cp.async.bulk.shared::cluster.global.mbarrier::complete_tx::bytes "
        "[%0], [%1], %2, [%3];"
        :: "r"(dst), "l"(src), "r"(bytes), "r"(mbar) : "memory");
}
__device__ __forceinline__ void mbar_wait(uint32_t a, uint32_t parity) {
    asm volatile(
        "{\n\t"
        ".reg .pred P;\n\t"
        "WAIT_%=:\n\t"
        "mbarrier.try_wait.parity.acquire.cta.shared::cta.b64 P, [%0], %1, 0x989680;\n\t"
        "@P bra.uni DONE_%=;\n\t"
        "bra.uni WAIT_%=;\n\t"
        "DONE_%=:\n\t"
        "}"
        :: "r"(a), "r"(parity) : "memory");
}
__device__ __forceinline__ void fence_async() {
    asm volatile("fence.proxy.async.shared::cta;" ::: "memory");
}

__global__ void __launch_bounds__(256, 4)
margin_loss_kernel(const float* __restrict__ x,
                   const int* __restrict__ labels,   // int32 (JAX x64 disabled)
                   float* __restrict__ out,
                   int N)
{
    __shared__ __align__(128) float sdata[2][TILE_FLOATS];   // 32 KB
    __shared__ __align__(16)  int   slab[2][RPT];
    __shared__ __align__(8)   unsigned long long smbar[2];
    __shared__ float warp_sums[8];
    __shared__ bool  is_last;

    const int tid  = threadIdx.x;
    const int warp = tid >> 5;
    const int lane = tid & 31;

    const int pRows = (N / P_DEN) * P_NUM;            // 212992: TMA / L2-persistent
    const int ntT   = pRows / RPT;                    // 6656 tiles
    const int nbL   = (N - pRows) / RPB;              // 12288 streaming batches
    const int nwarps = (NUM_BLOCKS * 256) >> 5;       // 4736
    const int wgid   = blockIdx.x * 8 + warp;

    const int cntT = (blockIdx.x < ntT) ? (ntT - 1 - blockIdx.x) / gridDim.x + 1 : 0;
    const int cntL = (wgid       < nbL) ? (nbL - 1 - wgid)       / nwarps     + 1 : 0;

    const float4* x4   = reinterpret_cast<const float4*>(x);
    const int4*   lab4 = reinterpret_cast<const int4*>(labels);

    if (tid == 0) {
        mbar_init(smem_u32(&smbar[0]), 1);
        mbar_init(smem_u32(&smbar[1]), 1);
        fence_async();
    }
    __syncthreads();

    // TMA prologue: fill both stages.
    if (tid == 0) {
        #pragma unroll
        for (int s = 0; s < 2; s++) {
            if (s < cntT) {
                const int t = blockIdx.x + s * gridDim.x;
                const uint32_t mb = smem_u32(&smbar[s]);
                mbar_expect_tx(mb, TILE_BYTES + LAB_BYTES);
                bulk_g2s(smem_u32(&sdata[s][0]), x + (size_t)t * TILE_FLOATS,
                         TILE_BYTES, mb);
                bulk_g2s(smem_u32(&slab[s][0]),  labels + (size_t)t * RPT,
                         LAB_BYTES, mb);
            }
        }
    }

    float wsum  = 0.0f;
    int   nrows = 0;

    // ── Streaming LDG state (rows [pRows, N), evict-first -> never displaces
    //    the persistent set in L2) ──
    float4 vA[RPB], vB[RPB];
    float  cA[RPB], cB[RPB];

    auto prefetchL = [&](int m, float4* vv, float* cc) {
        const int bb = wgid + m * nwarps;
        const size_t rbase = (size_t)pRows + (size_t)bb * RPB;
        const int4 L = __ldg(&lab4[(pRows >> 2) + bb]);
        cc[0] = __ldg(&x[(rbase + 0) * 128 + L.x]);
        cc[1] = __ldg(&x[(rbase + 1) * 128 + L.y]);
        cc[2] = __ldg(&x[(rbase + 2) * 128 + L.z]);
        cc[3] = __ldg(&x[(rbase + 3) * 128 + L.w]);
        #pragma unroll
        for (int j = 0; j < RPB; j++)
            vv[j] = __ldcs(&x4[(rbase + j) * 32 + lane]);   // streaming
    };
    auto computeL = [&](const float4* vv, const float* cc) {
        #pragma unroll
        for (int j = 0; j < RPB; j++) {
            const float m = MARGIN - cc[j];
            wsum += fmaxf(m + vv[j].x, 0.0f) + fmaxf(m + vv[j].y, 0.0f)
                  + fmaxf(m + vv[j].z, 0.0f) + fmaxf(m + vv[j].w, 0.0f);
        }
        nrows += RPB;
    };

    int m = 0;
    if (cntL > 0) prefetchL(0, vA, cA);

    // ── Main loop: one TMA tile per iteration; one LDG batch every 4th ──
    for (int k = 0; k < cntT; k++) {
        const bool doL = ((k & 3) == 0) && (m < cntL);
        if (doL && m + 1 < cntL) {
            if (m & 1) prefetchL(m + 1, vA, cA);
            else       prefetchL(m + 1, vB, cB);
        }

        // TMA tile: 4 smem rows per warp.
        const int s = k & 1;
        mbar_wait(smem_u32(&smbar[s]), (k >> 1) & 1);
        {
            const float* xs = sdata[s];
            #pragma unroll
            for (int rr = 0; rr < 4; rr++) {
                const int r   = warp * 4 + rr;
                const int lb  = slab[s][r];
                const float c = xs[r * 128 + lb];               // smem bcast
                const float4 v = reinterpret_cast<const float4*>(xs + r * 128)[lane];
                const float mg = MARGIN - c;
                wsum += fmaxf(mg + v.x, 0.0f) + fmaxf(mg + v.y, 0.0f)
                      + fmaxf(mg + v.z, 0.0f) + fmaxf(mg + v.w, 0.0f);
            }
            nrows += 4;
        }

        if (doL) {
            if (m & 1) computeL(vB, cB);
            else       computeL(vA, cA);
            m++;
        }

        __syncthreads();              // tile fully consumed
        if (tid == 0 && k + 2 < cntT) {
            const int t = blockIdx.x + (k + 2) * gridDim.x;
            fence_async();
            const uint32_t mb = smem_u32(&smbar[s]);
            mbar_expect_tx(mb, TILE_BYTES + LAB_BYTES);
            bulk_g2s(smem_u32(&sdata[s][0]), x + (size_t)t * TILE_FLOATS,
                     TILE_BYTES, mb);
            bulk_g2s(smem_u32(&slab[s][0]),  labels + (size_t)t * RPT,
                     LAB_BYTES, mb);
        }
    }

    // Drain leftover streaming batches (no barriers needed).
    while (m < cntL) {
        if (m + 1 < cntL) {
            if (m & 1) prefetchL(m + 1, vA, cA);
            else       prefetchL(m + 1, vB, cB);
        }
        if (m & 1) computeL(vB, cB);
        else       computeL(vA, cA);
        m++;
    }

    // Warp reduction; remove the j==label MARGIN term per processed row.
    #pragma unroll
    for (int o = 16; o > 0; o >>= 1)
        wsum += __shfl_down_sync(0xffffffffu, wsum, o);
    if (lane == 0) warp_sums[warp] = wsum - MARGIN * (float)nrows;

    __syncthreads();

    if (tid == 0) {
        double bsum = 0.0;
        #pragma unroll
        for (int wi = 0; wi < 8; wi++) bsum += (double)warp_sums[wi];
        atomicAdd(&g_total, bsum);
        __threadfence();
        unsigned int t = atomicAdd(&g_count, 1u);
        is_last = (t == gridDim.x - 1);
    }
    __syncthreads();

    if (is_last && tid == 0) {
        const double total = g_total;
        // mean over N * (G-1) pairs, G = 128
        out[0] = (float)(total / ((double)N * 127.0));
        g_total = 0.0;
        g_count = 0u;
    }
}

extern "C" void kernel_launch(void* const* d_in, const int* in_sizes, int n_in,
                              void* d_out, int out_size)
{
    const float* x      = (const float*)d_in[0];
    const int*   labels = (const int*)d_in[1];
    float*       out    = (float*)d_out;

    const int N = in_sizes[1];                  // labels count = rows

    margin_loss_kernel<<<NUM_BLOCKS, 256>>>(x, labels, out, N);
}

// round 14
// speedup vs baseline: 1.2588x; 1.2588x over previous
#include <cuda_runtime.h>
#include <cstdint>

#define MARGIN 0.1f
#define RPT 32                          // rows per TMA tile
#define TILE_FLOATS (RPT * 128)         // 4096
#define TILE_BYTES  (TILE_FLOATS * 4)   // 16384
#define LAB_BYTES   (RPT * 4)           // 128
#define RPB 4                           // rows per LDG batch
#define NUM_BLOCKS 592                  // 148 SMs * 4 CTAs
// Persistent (L2-retained, TMA/evict-normal) fraction of rows: 10/16 = 5/8.
// 5/8 * 262144 rows * 512 B = 83.9 MB — comfortably under L2's retention
// capacity (109 MB thrashed in R13; 67 MB retained in R12).
#define P_NUM 10
#define P_DEN 16

// Persistent device scratch; reset by last block each call (graph-replay safe).
__device__ double       g_total = 0.0;
__device__ unsigned int g_count = 0u;

__device__ __forceinline__ uint32_t smem_u32(const void* p) {
    return (uint32_t)__cvta_generic_to_shared(p);
}
__device__ __forceinline__ void mbar_init(uint32_t a, uint32_t cnt) {
    asm volatile("mbarrier.init.shared.b64 [%0], %1;" :: "r"(a), "r"(cnt) : "memory");
}
__device__ __forceinline__ void mbar_expect_tx(uint32_t a, uint32_t bytes) {
    asm volatile("mbarrier.arrive.expect_tx.shared.b64 _, [%0], %1;"
                 :: "r"(a), "r"(bytes) : "memory");
}
__device__ __forceinline__ void bulk_g2s(uint32_t dst, const void* src,
                                         uint32_t bytes, uint32_t mbar) {
    asm volatile(
        "cp.async.bulk.shared::cluster.global.mbarrier::complete_tx::bytes "
        "[%0], [%1], %2, [%3];"
        :: "r"(dst), "l"(src), "r"(bytes), "r"(mbar) : "memory");
}
__device__ __forceinline__ void mbar_wait(uint32_t a, uint32_t parity) {
    asm volatile(
        "{\n\t"
        ".reg .pred P;\n\t"
        "WAIT_%=:\n\t"
        "mbarrier.try_wait.parity.acquire.cta.shared::cta.b64 P, [%0], %1, 0x989680;\n\t"
        "@P bra.uni DONE_%=;\n\t"
        "bra.uni WAIT_%=;\n\t"
        "DONE_%=:\n\t"
        "}"
        :: "r"(a), "r"(parity) : "memory");
}
__device__ __forceinline__ void fence_async() {
    asm volatile("fence.proxy.async.shared::cta;" ::: "memory");
}

__global__ void __launch_bounds__(256, 4)
margin_loss_kernel(const float* __restrict__ x,
                   const int* __restrict__ labels,   // int32 (JAX x64 disabled)
                   float* __restrict__ out,
                   int N)
{
    __shared__ __align__(128) float sdata[2][TILE_FLOATS];   // 32 KB
    __shared__ __align__(16)  int   slab[2][RPT];
    __shared__ __align__(8)   unsigned long long smbar[2];
    __shared__ float warp_sums[8];
    __shared__ bool  is_last;

    const int tid  = threadIdx.x;
    const int warp = tid >> 5;
    const int lane = tid & 31;

    const int pRows = (N / P_DEN) * P_NUM;            // 163840: TMA / L2-persistent
    const int ntT   = pRows / RPT;                    // 5120 tiles
    const int nbL   = (N - pRows) / RPB;              // 24576 streaming batches
    const int nwarps = (NUM_BLOCKS * 256) >> 5;       // 4736
    const int wgid   = blockIdx.x * 8 + warp;

    const int cntT = (blockIdx.x < ntT) ? (ntT - 1 - blockIdx.x) / gridDim.x + 1 : 0;
    const int cntL = (wgid       < nbL) ? (nbL - 1 - wgid)       / nwarps     + 1 : 0;

    const float4* x4   = reinterpret_cast<const float4*>(x);
    const int4*   lab4 = reinterpret_cast<const int4*>(labels);

    if (tid == 0) {
        mbar_init(smem_u32(&smbar[0]), 1);
        mbar_init(smem_u32(&smbar[1]), 1);
        fence_async();
    }
    __syncthreads();

    // TMA prologue: fill both stages.
    if (tid == 0) {
        #pragma unroll
        for (int s = 0; s < 2; s++) {
            if (s < cntT) {
                const int t = blockIdx.x + s * gridDim.x;
                const uint32_t mb = smem_u32(&smbar[s]);
                mbar_expect_tx(mb, TILE_BYTES + LAB_BYTES);
                bulk_g2s(smem_u32(&sdata[s][0]), x + (size_t)t * TILE_FLOATS,
                         TILE_BYTES, mb);
                bulk_g2s(smem_u32(&slab[s][0]),  labels + (size_t)t * RPT,
                         LAB_BYTES, mb);
            }
        }
    }

    float wsum  = 0.0f;
    int   nrows = 0;

    // ── Streaming LDG state (rows [pRows, N), evict-first -> never displaces
    //    the persistent set in L2) ──
    float4 vA[RPB], vB[RPB];
    float  cA[RPB], cB[RPB];

    auto prefetchL = [&](int m, float4* vv, float* cc) {
        const int bb = wgid + m * nwarps;
        const size_t rbase = (size_t)pRows + (size_t)bb * RPB;
        const int4 L = __ldg(&lab4[(pRows >> 2) + bb]);
        cc[0] = __ldg(&x[(rbase + 0) * 128 + L.x]);
        cc[1] = __ldg(&x[(rbase + 1) * 128 + L.y]);
        cc[2] = __ldg(&x[(rbase + 2) * 128 + L.z]);
        cc[3] = __ldg(&x[(rbase + 3) * 128 + L.w]);
        #pragma unroll
        for (int j = 0; j < RPB; j++)
            vv[j] = __ldcs(&x4[(rbase + j) * 32 + lane]);   // streaming
    };
    auto computeL = [&](const float4* vv, const float* cc) {
        #pragma unroll
        for (int j = 0; j < RPB; j++) {
            const float m = MARGIN - cc[j];
            wsum += fmaxf(m + vv[j].x, 0.0f) + fmaxf(m + vv[j].y, 0.0f)
                  + fmaxf(m + vv[j].z, 0.0f) + fmaxf(m + vv[j].w, 0.0f);
        }
        nrows += RPB;
    };

    int m = 0;
    if (cntL > 0) prefetchL(0, vA, cA);

    // ── Main loop: one TMA tile per iteration; one LDG batch every other ──
    for (int k = 0; k < cntT; k++) {
        const bool doL = ((k & 1) == 0) && (m < cntL);
        if (doL && m + 1 < cntL) {
            if (m & 1) prefetchL(m + 1, vA, cA);
            else       prefetchL(m + 1, vB, cB);
        }

        // TMA tile: 4 smem rows per warp.
        const int s = k & 1;
        mbar_wait(smem_u32(&smbar[s]), (k >> 1) & 1);
        {
            const float* xs = sdata[s];
            #pragma unroll
            for (int rr = 0; rr < 4; rr++) {
                const int r   = warp * 4 + rr;
                const int lb  = slab[s][r];
                const float c = xs[r * 128 + lb];               // smem bcast
                const float4 v = reinterpret_cast<const float4*>(xs + r * 128)[lane];
                const float mg = MARGIN - c;
                wsum += fmaxf(mg + v.x, 0.0f) + fmaxf(mg + v.y, 0.0f)
                      + fmaxf(mg + v.z, 0.0f) + fmaxf(mg + v.w, 0.0f);
            }
            nrows += 4;
        }

        if (doL) {
            if (m & 1) computeL(vB, cB);
            else       computeL(vA, cA);
            m++;
        }

        __syncthreads();              // tile fully consumed
        if (tid == 0 && k + 2 < cntT) {
            const int t = blockIdx.x + (k + 2) * gridDim.x;
            fence_async();
            const uint32_t mb = smem_u32(&smbar[s]);
            mbar_expect_tx(mb, TILE_BYTES + LAB_BYTES);
            bulk_g2s(smem_u32(&sdata[s][0]), x + (size_t)t * TILE_FLOATS,
                     TILE_BYTES, mb);
            bulk_g2s(smem_u32(&slab[s][0]),  labels + (size_t)t * RPT,
                     LAB_BYTES, mb);
        }
    }

    // Drain leftover streaming batches (no barriers needed).
    while (m < cntL) {
        if (m + 1 < cntL) {
            if (m & 1) prefetchL(m + 1, vA, cA);
            else       prefetchL(m + 1, vB, cB);
        }
        if (m & 1) computeL(vB, cB);
        else       computeL(vA, cA);
        m++;
    }

    // Warp reduction; remove the j==label MARGIN term per processed row.
    #pragma unroll
    for (int o = 16; o > 0; o >>= 1)
        wsum += __shfl_down_sync(0xffffffffu, wsum, o);
    if (lane == 0) warp_sums[warp] = wsum - MARGIN * (float)nrows;

    __syncthreads();

    if (tid == 0) {
        double bsum = 0.0;
        #pragma unroll
        for (int wi = 0; wi < 8; wi++) bsum += (double)warp_sums[wi];
        atomicAdd(&g_total, bsum);
        __threadfence();
        unsigned int t = atomicAdd(&g_count, 1u);
        is_last = (t == gridDim.x - 1);
    }
    __syncthreads();

    if (is_last && tid == 0) {
        const double total = g_total;
        // mean over N * (G-1) pairs, G = 128
        out[0] = (float)(total / ((double)N * 127.0));
        g_total = 0.0;
        g_count = 0u;
    }
}

extern "C" void kernel_launch(void* const* d_in, const int* in_sizes, int n_in,
                              void* d_out, int out_size)
{
    const float* x      = (const float*)d_in[0];
    const int*   labels = (const int*)d_in[1];
    float*       out    = (float*)d_out;

    const int N = in_sizes[1];                  // labels count = rows

    margin_loss_kernel<<<NUM_BLOCKS, 256>>>(x, labels, out, N);
}